// round 2
// baseline (speedup 1.0000x reference)
#include <cuda_runtime.h>

#define TOT 8192
#define BN 16
#define C 64
#define K 20
#define CN 512
#define NW (BN*CN)          // 8192 walkers
#define STEPS 8
#define NBLK 512
#define BN_EPS 1e-5f

// ---- device scratch (static; no allocations) ----
__device__ float g_xT[(size_t)BN*TOT*C];          // x transposed (b, node, ch)  32MB
__device__ float g_curves[(size_t)STEPS*NW*C];    // curve scratch [step][w][ch] 16MB
__device__ float g_S[2][BN*2*CN];                 // double-buffered softmax exchange
__device__ unsigned g_bar;                        // grid barrier counter

// ---------------- transpose x (b,c,tot) -> xT (b,tot,c) ----------------
__global__ void transpose_x_kernel(const float* __restrict__ x) {
    __shared__ float tile[32][33];
    int b = blockIdx.z;
    int node0 = blockIdx.x * 32;
    int ch0 = blockIdx.y * 32;
    int tx = threadIdx.x, ty = threadIdx.y;   // 32 x 8
    const float* xb = x + (size_t)b * C * TOT;
    #pragma unroll
    for (int i = 0; i < 32; i += 8)
        tile[ty + i][tx] = xb[(size_t)(ch0 + ty + i) * TOT + node0 + tx];
    __syncthreads();
    float* xTb = g_xT + (size_t)b * TOT * C;
    #pragma unroll
    for (int i = 0; i < 32; i += 8)
        xTb[(size_t)(node0 + ty + i) * C + ch0 + tx] = tile[tx][ty + i];
}

__device__ __forceinline__ float dot4(const float4& a, const float4& b) {
    return a.x*b.x + a.y*b.y + a.z*b.z + a.w*b.w;
}

// ---------------- persistent walk: all 8 steps in one kernel ----------------
// 16 lanes per walker (2 walkers/warp). Lane sub owns channels [4*sub..4*sub+3].
__global__ __launch_bounds__(256, 4)
void walk_persistent(
    const int* __restrict__ adj, const int* __restrict__ cur0,
    const float* __restrict__ agent_w,
    const float* __restrict__ agent_gamma, const float* __restrict__ agent_beta,
    const float* __restrict__ agent_mean,  const float* __restrict__ agent_var,
    const float* __restrict__ mom_w,
    const float* __restrict__ mom_gamma, const float* __restrict__ mom_beta,
    const float* __restrict__ mom_mean,  const float* __restrict__ mom_var)
{
    int sub = threadIdx.x & 15;
    int w = blockIdx.x * 16 + (threadIdx.x >> 4);
    int b = w >> 9;
    int n = w & 511;

    const float4* wv = (const float4*)agent_w;        // 32 float4
    float4 wl = __ldg(&wv[sub]);                      // agent_w[4sub..4sub+3]
    float4 wh = __ldg(&wv[16 + sub]);                 // agent_w[64+4sub..]

    float inv_a  = __ldg(agent_gamma) / sqrtf(__ldg(agent_var) + BN_EPS);
    float mean_a = __ldg(agent_mean);
    float beta_a = __ldg(agent_beta);

    const float* xTb = g_xT + (size_t)b * TOT * C;
    int cidx = __ldg(&cur0[w]);

    float4 cf = make_float4(0.f,0.f,0.f,0.f);
    float4 pf = cf;

    for (int step = 0; step < STEPS; step++) {
        float4 cv = make_float4(0.f,0.f,0.f,0.f);
        float tppp, n1pp = 0.f;
        if (step == 0) {
            const float4* pv = (const float4*)(xTb + (size_t)cidx * C);
            pf = __ldg(&pv[sub]);
        } else {
            // att scramble: walker n uses flat softmax entries 2n and 2n+1
            float a0 = __ldcg(&g_S[(step - 1) & 1][b * 1024 + 2 * n]);
            float a1 = __ldcg(&g_S[(step - 1) & 1][b * 1024 + 2 * n + 1]);
            pf.x = cf.x*a0 + pf.x*a1;  pf.y = cf.y*a0 + pf.y*a1;
            pf.z = cf.z*a0 + pf.z*a1;  pf.w = cf.w*a0 + pf.w*a1;
            cv.x = cf.x - pf.x; cv.y = cf.y - pf.y;
            cv.z = cf.z - pf.z; cv.w = cf.w - pf.w;
            n1pp = dot4(cv, cv);
        }
        tppp = dot4(pf, wh);
        #pragma unroll
        for (int off = 1; off <= 8; off <<= 1) {
            tppp += __shfl_xor_sync(0xffffffffu, tppp, off);
            n1pp += __shfl_xor_sync(0xffffffffu, n1pp, off);
        }
        float n1 = sqrtf(n1pp);

        const int* adjp = adj + ((size_t)b * TOT + cidx) * K;
        float best = -3.4e38f; int ksel = 0;

        #pragma unroll 4
        for (int k = 0; k < K; k++) {
            int idx = __ldg(&adjp[k]);
            const float4* pv = (const float4*)(xTb + (size_t)idx * C);
            float4 p = __ldg(&pv[sub]);
            float accp = dot4(p, wl);
            float ccp = 0.f, nnp = 0.f;
            if (step != 0) {
                float d0 = p.x - cf.x, d1 = p.y - cf.y;
                float d2 = p.z - cf.z, d3 = p.w - cf.w;
                ccp = cv.x*d0 + cv.y*d1 + cv.z*d2 + cv.w*d3;
                nnp = d0*d0 + d1*d1 + d2*d2 + d3*d3;
            }
            #pragma unroll
            for (int off = 1; off <= 8; off <<= 1) {
                accp += __shfl_xor_sync(0xffffffffu, accp, off);
                if (step != 0) {
                    ccp += __shfl_xor_sync(0xffffffffu, ccp, off);
                    nnp += __shfl_xor_sync(0xffffffffu, nnp, off);
                }
            }
            float lg = (accp + tppp - mean_a) * inv_a + beta_a;
            if (step != 0) {
                float cosv = ccp / fmaxf(n1 * sqrtf(nnp), 1e-8f);
                lg *= fminf(fmaxf(1.f + cosv, 0.f), 1.f);
            }
            if (lg > best) { best = lg; ksel = k; }
        }

        int nidx = __ldg(&adjp[ksel]);
        {
            const float4* pv = (const float4*)(xTb + (size_t)nidx * C);
            cf = __ldg(&pv[sub]);
        }
        cidx = nidx;

        // coalesced curve store: [step][w][ch]
        ((float4*)(g_curves + ((size_t)step * NW + w) * C))[sub] = cf;

        if (step < STEPS - 1) {
            // mlog for next step: mom_w @ [cur_feature; pre_feature]
            const float4* mv = (const float4*)mom_w;  // 2 rows x 32 float4
            float l0 = dot4(cf, __ldg(&mv[sub]))      + dot4(pf, __ldg(&mv[16 + sub]));
            float l1 = dot4(cf, __ldg(&mv[32 + sub])) + dot4(pf, __ldg(&mv[48 + sub]));
            #pragma unroll
            for (int off = 1; off <= 8; off <<= 1) {
                l0 += __shfl_xor_sync(0xffffffffu, l0, off);
                l1 += __shfl_xor_sync(0xffffffffu, l1, off);
            }
            if (sub == 0) {
                float inv0 = __ldg(&mom_gamma[0]) / sqrtf(__ldg(&mom_var[0]) + BN_EPS);
                float inv1 = __ldg(&mom_gamma[1]) / sqrtf(__ldg(&mom_var[1]) + BN_EPS);
                float m0 = (l0 - __ldg(&mom_mean[0])) * inv0 + __ldg(&mom_beta[0]);
                float m1 = (l1 - __ldg(&mom_mean[1])) * inv1 + __ldg(&mom_beta[1]);
                float mx = fmaxf(m0, m1);
                float e0 = expf(m0 - mx), e1 = expf(m1 - mx);
                float s = e0 + e1;
                g_S[step & 1][b * 1024 + n]       = e0 / s;
                g_S[step & 1][b * 1024 + 512 + n] = e1 / s;
            }
            // ---- grid barrier (all 512 blocks are resident by launch_bounds) ----
            __syncthreads();
            if (threadIdx.x == 0) {
                __threadfence();
                atomicAdd(&g_bar, 1u);
                unsigned target = (unsigned)(step + 1) * NBLK;
                while (*((volatile unsigned*)&g_bar) < target) { }
                __threadfence();
            }
            __syncthreads();
        }
    }
}

// ---------------- reorder: g_curves[step][w][ch] -> out[b][ch][n][step] ----------------
__global__ __launch_bounds__(256)
void reorder_kernel(float* __restrict__ out) {
    __shared__ float tile[16][8 * C + 1];   // [i][step*64+ch], padded row
    int b = blockIdx.x >> 5;
    int n0 = (blockIdx.x & 31) * 16;
    int t = threadIdx.x;

    #pragma unroll
    for (int step = 0; step < STEPS; step++) {
        #pragma unroll
        for (int i4 = 0; i4 < 4; i4++) {
            int i = i4 * 4 + (t >> 6);
            int ch = t & 63;
            int w = b * CN + n0 + i;
            tile[i][step * 64 + ch] =
                g_curves[((size_t)step * NW + w) * C + ch];
        }
    }
    __syncthreads();

    int i = t & 15, ch0 = t >> 4;
    #pragma unroll
    for (int cc = 0; cc < 4; cc++) {
        int ch = ch0 + cc * 16;
        float v[8];
        #pragma unroll
        for (int s = 0; s < STEPS; s++) v[s] = tile[i][s * 64 + ch];
        float4* dst = (float4*)(out +
            ((((size_t)b * C + ch) * CN) + n0 + i) * STEPS);
        dst[0] = make_float4(v[0], v[1], v[2], v[3]);
        dst[1] = make_float4(v[4], v[5], v[6], v[7]);
    }
}

extern "C" void kernel_launch(void* const* d_in, const int* in_sizes, int n_in,
                              void* d_out, int out_size) {
    const float* x          = (const float*)d_in[1];
    const int*   adj        = (const int*)  d_in[2];
    const int*   cur        = (const int*)  d_in[3];
    const float* agent_w    = (const float*)d_in[4];
    const float* agent_gamma= (const float*)d_in[5];
    const float* agent_beta = (const float*)d_in[6];
    const float* agent_mean = (const float*)d_in[7];
    const float* agent_var  = (const float*)d_in[8];
    const float* mom_w      = (const float*)d_in[9];
    const float* mom_gamma  = (const float*)d_in[10];
    const float* mom_beta   = (const float*)d_in[11];
    const float* mom_mean   = (const float*)d_in[12];
    const float* mom_var    = (const float*)d_in[13];
    float* out = (float*)d_out;

    // reset grid-barrier counter (memset node is graph-capturable)
    void* bar_addr = nullptr;
    cudaGetSymbolAddress(&bar_addr, g_bar);
    cudaMemsetAsync(bar_addr, 0, sizeof(unsigned));

    dim3 tb(32, 8), tg(TOT / 32, C / 32, BN);
    transpose_x_kernel<<<tg, tb>>>(x);

    walk_persistent<<<NBLK, 256>>>(adj, cur, agent_w, agent_gamma, agent_beta,
        agent_mean, agent_var, mom_w, mom_gamma, mom_beta, mom_mean, mom_var);

    reorder_kernel<<<BN * (CN / 16), 256>>>(out);
}